// round 15
// baseline (speedup 1.0000x reference)
#include <cuda_runtime.h>
#include <cstdint>

// ---------------------------------------------------------------------------
// Problem constants: N=50000 nodes, E=1.6M edges, D_IN=512, H=64, D_OUT=64.
// ---------------------------------------------------------------------------
#define MAX_N 50048
#define MAX_E 1600000
#define HDIM  64
#define SCAN_B 512

// Scratch (device globals — allocation-free rule)
__device__ __align__(256) float g_buf_a[MAX_N * HDIM];   // xW
__device__ __align__(256) float g_buf_b[MAX_N * HDIM];   // agg
__device__ __align__(256) float g_dinv[MAX_N];           // deg^{-1/2}
__device__ __align__(256) int   g_cnt[MAX_N];            // in-degree counts
__device__ __align__(256) int   g_off[MAX_N + 1];        // CSR offsets
__device__ __align__(256) int   g_cur[MAX_N];            // fill cursors
__device__ __align__(256) int   g_parts[256];            // scan partials
__device__ __align__(256) int   g_src_s[MAX_E];          // CSR: source node
__device__ __align__(256) float g_nrm_s[MAX_E];          // CSR: edge norm

// ---------------------------------------------------------------------------
__device__ __forceinline__ float selu_f(float x) {
    const float sc = 1.0507009873554805f;
    const float al = 1.6732632423543772f;
    return x > 0.0f ? sc * x : sc * al * (expf(x) - 1.0f);
}

// ---------------------------------------------------------------------------
// Degree + in-degree count (one pass over edges)
// ---------------------------------------------------------------------------
__global__ void init_kernel(float* __restrict__ deg, int* __restrict__ cnt, int n) {
    int i = blockIdx.x * blockDim.x + threadIdx.x;
    if (i < n) { deg[i] = 1.0f; cnt[i] = 0; }   // deg starts at self-loop w=1
}

__global__ void count_deg_kernel(const int* __restrict__ col,
                                 const float* __restrict__ w,
                                 float* __restrict__ deg,
                                 int* __restrict__ cnt, int e) {
    int i = blockIdx.x * blockDim.x + threadIdx.x;
    if (i < e) {
        int c = col[i];
        atomicAdd(&deg[c], w[i]);
        atomicAdd(&cnt[c], 1);
    }
}

__global__ void deg_inv_kernel(float* __restrict__ deg, int n) {
    int i = blockIdx.x * blockDim.x + threadIdx.x;
    if (i < n) {
        float d = deg[i];
        deg[i] = d > 0.0f ? rsqrtf(d) : 0.0f;
    }
}

// ---------------------------------------------------------------------------
// Exclusive scan of cnt[0..n) into off[0..n], off[n]=e.  3 phases.
// ---------------------------------------------------------------------------
__global__ void scan1_kernel(const int* __restrict__ cnt, int* __restrict__ off,
                             int* __restrict__ partials, int n) {
    __shared__ int s[SCAN_B];
    int t = threadIdx.x;
    int idx = blockIdx.x * SCAN_B + t;
    int v = (idx < n) ? cnt[idx] : 0;
    s[t] = v;
    __syncthreads();
    for (int d = 1; d < SCAN_B; d <<= 1) {
        int x = (t >= d) ? s[t - d] : 0;
        __syncthreads();
        s[t] += x;
        __syncthreads();
    }
    if (idx < n) off[idx] = s[t] - v;          // exclusive within block
    if (t == SCAN_B - 1) partials[blockIdx.x] = s[t];  // block total
}

__global__ void scan2_kernel(int* __restrict__ partials, int nb) {
    if (threadIdx.x == 0 && blockIdx.x == 0) {
        int run = 0;
        for (int i = 0; i < nb; i++) {
            int v = partials[i];
            partials[i] = run;
            run += v;
        }
    }
}

__global__ void scan3_kernel(int* __restrict__ off, const int* __restrict__ partials,
                             int* __restrict__ cur, int n, int e) {
    int i = blockIdx.x * blockDim.x + threadIdx.x;
    if (i < n) {
        off[i] += partials[i / SCAN_B];
        cur[i] = 0;
    }
    if (i == 0) off[n] = e;
}

// ---------------------------------------------------------------------------
// CSR fill: place each edge into its destination's segment; norm inline.
// ---------------------------------------------------------------------------
__global__ void fill_kernel(const int* __restrict__ row, const int* __restrict__ col,
                            const float* __restrict__ w, const float* __restrict__ dinv,
                            const int* __restrict__ off, int* __restrict__ cur,
                            int* __restrict__ src_s, float* __restrict__ nrm_s, int e) {
    int i = blockIdx.x * blockDim.x + threadIdx.x;
    if (i < e) {
        int r = row[i];
        int c = col[i];
        int slot = off[c] + atomicAdd(&cur[c], 1);
        src_s[slot] = r;
        nrm_s[slot] = __ldg(dinv + r) * w[i] * __ldg(dinv + c);
    }
}

// ---------------------------------------------------------------------------
// Tiled SGEMM: C[M x 64] = A'[M x K] @ B[K x 64], A' = A or selu(A + biasIn)
// (PREACT fuses the previous layer's bias+SELU into the A-tile load).
// BM=64, BN=64, BK=32, 256 threads, 4x4 microtile.
// ---------------------------------------------------------------------------
template <int K, bool PREACT>
__global__ void __launch_bounds__(256)
gemm_kernel(const float* __restrict__ A, const float* __restrict__ B,
            const float* __restrict__ biasIn, float* __restrict__ C, int M) {
    constexpr int BM = 64, BN = 64, BK = 32;
    __shared__ float As[BK][BM + 1];
    __shared__ float Bs[BK][BN];

    const int tid = threadIdx.x;
    const int tx = tid & 15;
    const int ty = tid >> 4;
    const int row0 = blockIdx.x * BM;

    const int ar = tid >> 3;           // 0..31
    const int ac = (tid & 7) * 4;      // 0..28
    const int br = tid >> 4;           // 0..15
    const int bc = (tid & 15) * 4;     // 0..60

    float acc[4][4];
#pragma unroll
    for (int i = 0; i < 4; i++)
#pragma unroll
        for (int j = 0; j < 4; j++) acc[i][j] = 0.0f;

    for (int k0 = 0; k0 < K; k0 += BK) {
#pragma unroll
        for (int h = 0; h < 2; h++) {
            int r = ar + h * 32;
            int grow = row0 + r;
            float4 v = make_float4(0.f, 0.f, 0.f, 0.f);
            if (grow < M)
                v = *reinterpret_cast<const float4*>(A + (size_t)grow * K + k0 + ac);
            if (PREACT) {
                float4 b = *reinterpret_cast<const float4*>(biasIn + k0 + ac);
                v.x = selu_f(v.x + b.x);
                v.y = selu_f(v.y + b.y);
                v.z = selu_f(v.z + b.z);
                v.w = selu_f(v.w + b.w);
            }
            As[ac + 0][r] = v.x;
            As[ac + 1][r] = v.y;
            As[ac + 2][r] = v.z;
            As[ac + 3][r] = v.w;
        }
#pragma unroll
        for (int h = 0; h < 2; h++) {
            int r = br + h * 16;
            float4 v = *reinterpret_cast<const float4*>(B + (size_t)(k0 + r) * BN + bc);
            *reinterpret_cast<float4*>(&Bs[r][bc]) = v;
        }
        __syncthreads();

#pragma unroll
        for (int kk = 0; kk < BK; kk++) {
            float a[4];
#pragma unroll
            for (int i = 0; i < 4; i++) a[i] = As[kk][ty * 4 + i];
            float4 b4 = *reinterpret_cast<const float4*>(&Bs[kk][tx * 4]);
            float b[4] = {b4.x, b4.y, b4.z, b4.w};
#pragma unroll
            for (int i = 0; i < 4; i++)
#pragma unroll
                for (int j = 0; j < 4; j++) acc[i][j] += a[i] * b[j];
        }
        __syncthreads();
    }

#pragma unroll
    for (int i = 0; i < 4; i++) {
        int gr = row0 + ty * 4 + i;
        if (gr >= M) continue;
#pragma unroll
        for (int j = 0; j < 4; j++)
            C[(size_t)gr * 64 + tx * 4 + j] = acc[i][j];
    }
}

// ---------------------------------------------------------------------------
// CSR gather aggregation: one HALF-WARP per destination node, ZERO atomics.
// Each of 16 lanes owns one float4 of the 64 feature dims. Self-loop term
// folded in. Unroll-4 over incident edges for memory-level parallelism.
// ---------------------------------------------------------------------------
__global__ void __launch_bounds__(256)
gather_kernel(const float* __restrict__ xw,
              const int* __restrict__ src_s, const float* __restrict__ nrm_s,
              const int* __restrict__ off, const float* __restrict__ dinv,
              float* __restrict__ agg, int n) {
    int hw = (blockIdx.x * blockDim.x + threadIdx.x) >> 4;   // half-warp id = node
    int lane = threadIdx.x & 15;
    if (hw >= n) return;

    const float4* xw4 = reinterpret_cast<const float4*>(xw);

    int beg = __ldg(off + hw);
    int end = __ldg(off + hw + 1);

    // self-loop: xw[node] * dinv^2
    float d = __ldg(dinv + hw);
    float s = d * d;
    float4 a0 = __ldg(xw4 + (size_t)hw * 16 + lane);
    float4 acc = make_float4(a0.x * s, a0.y * s, a0.z * s, a0.w * s);

    int i = beg;
    for (; i + 4 <= end; i += 4) {
        int s0 = __ldg(src_s + i + 0);
        int s1 = __ldg(src_s + i + 1);
        int s2 = __ldg(src_s + i + 2);
        int s3 = __ldg(src_s + i + 3);
        float n0 = __ldg(nrm_s + i + 0);
        float n1 = __ldg(nrm_s + i + 1);
        float n2 = __ldg(nrm_s + i + 2);
        float n3 = __ldg(nrm_s + i + 3);
        float4 v0 = __ldg(xw4 + (size_t)s0 * 16 + lane);
        float4 v1 = __ldg(xw4 + (size_t)s1 * 16 + lane);
        float4 v2 = __ldg(xw4 + (size_t)s2 * 16 + lane);
        float4 v3 = __ldg(xw4 + (size_t)s3 * 16 + lane);
        acc.x += n0 * v0.x + n1 * v1.x + n2 * v2.x + n3 * v3.x;
        acc.y += n0 * v0.y + n1 * v1.y + n2 * v2.y + n3 * v3.y;
        acc.z += n0 * v0.z + n1 * v1.z + n2 * v2.z + n3 * v3.z;
        acc.w += n0 * v0.w + n1 * v1.w + n2 * v2.w + n3 * v3.w;
    }
    for (; i < end; i++) {
        int sr = __ldg(src_s + i);
        float nm = __ldg(nrm_s + i);
        float4 v = __ldg(xw4 + (size_t)sr * 16 + lane);
        acc.x += nm * v.x;
        acc.y += nm * v.y;
        acc.z += nm * v.z;
        acc.w += nm * v.w;
    }

    reinterpret_cast<float4*>(agg + (size_t)hw * 64)[lane] = acc;
}

// ---------------------------------------------------------------------------
// Fused MLP: out = selu(selu(selu(selu(agg+gb)W0+b0)W1+b1)W2+b2)W3+b3
// One block = 64 rows; 33 KB static smem (single in-place Hs buffer).
// ---------------------------------------------------------------------------
__global__ void __launch_bounds__(256)
fused_mlp_kernel(const float* __restrict__ agg, const float* __restrict__ gb,
                 const float* __restrict__ W0, const float* __restrict__ b0,
                 const float* __restrict__ W1, const float* __restrict__ b1,
                 const float* __restrict__ W2, const float* __restrict__ b2,
                 const float* __restrict__ W3, const float* __restrict__ b3,
                 float* __restrict__ out, int M) {
    __shared__ float Hs[HDIM][HDIM + 1];  // [k][row], transposed, padded
    __shared__ float Ws[HDIM][HDIM];      // [k][out]

    const int tid = threadIdx.x;
    const int tx = tid & 15;
    const int ty = tid >> 4;
    const int row0 = blockIdx.x * 64;

    {
        const int lr = tid >> 2;
        const int lc = (tid & 3) * 16;
        int grow = row0 + lr;
#pragma unroll
        for (int q = 0; q < 4; q++) {
            int k = lc + q * 4;
            float4 v = make_float4(0.f, 0.f, 0.f, 0.f);
            if (grow < M)
                v = *reinterpret_cast<const float4*>(agg + (size_t)grow * 64 + k);
            float4 b = *reinterpret_cast<const float4*>(gb + k);
            Hs[k + 0][lr] = selu_f(v.x + b.x);
            Hs[k + 1][lr] = selu_f(v.y + b.y);
            Hs[k + 2][lr] = selu_f(v.z + b.z);
            Hs[k + 3][lr] = selu_f(v.w + b.w);
        }
    }

    const float* Wl[4] = {W0, W1, W2, W3};
    const float* bl[4] = {b0, b1, b2, b3};

    for (int layer = 0; layer < 4; layer++) {
        {
            const int lr = tid >> 2;
            const int lc = (tid & 3) * 16;
            const float* W = Wl[layer];
#pragma unroll
            for (int q = 0; q < 4; q++) {
                int c0 = lc + q * 4;
                *reinterpret_cast<float4*>(&Ws[lr][c0]) =
                    *reinterpret_cast<const float4*>(W + (size_t)lr * 64 + c0);
            }
        }
        __syncthreads();

        float acc[4][4];
#pragma unroll
        for (int i = 0; i < 4; i++)
#pragma unroll
            for (int j = 0; j < 4; j++) acc[i][j] = 0.0f;

#pragma unroll 16
        for (int kk = 0; kk < HDIM; kk++) {
            float a[4];
#pragma unroll
            for (int i = 0; i < 4; i++) a[i] = Hs[kk][ty * 4 + i];
            float4 b4 = *reinterpret_cast<const float4*>(&Ws[kk][tx * 4]);
            float b[4] = {b4.x, b4.y, b4.z, b4.w};
#pragma unroll
            for (int i = 0; i < 4; i++)
#pragma unroll
                for (int j = 0; j < 4; j++) acc[i][j] += a[i] * b[j];
        }

        float4 bb = *reinterpret_cast<const float4*>(bl[layer] + tx * 4);
        float bias4[4] = {bb.x, bb.y, bb.z, bb.w};

        if (layer < 3) {
            __syncthreads();
#pragma unroll
            for (int i = 0; i < 4; i++)
#pragma unroll
                for (int j = 0; j < 4; j++)
                    Hs[tx * 4 + j][ty * 4 + i] = selu_f(acc[i][j] + bias4[j]);
            __syncthreads();
        } else {
#pragma unroll
            for (int i = 0; i < 4; i++) {
                int gr = row0 + ty * 4 + i;
                if (gr >= M) continue;
#pragma unroll
                for (int j = 0; j < 4; j++)
                    out[(size_t)gr * 64 + tx * 4 + j] = acc[i][j] + bias4[j];
            }
        }
    }
}

// ---------------------------------------------------------------------------
// Launch.  Inputs (metadata order):
//  0 x[N,512] 1 edge_index[2,E] 2 edge_attrs[E]
//  3 gW1 4 gb1 5 gW2 6 gb2 7 W0 8 b0 9 W1 10 b1 11 W2 12 b2 13 W3 14 b3
// Output: float32 [N,64]
// ---------------------------------------------------------------------------
extern "C" void kernel_launch(void* const* d_in, const int* in_sizes, int n_in,
                              void* d_out, int out_size) {
    const float* x    = (const float*)d_in[0];
    const int*   ei   = (const int*)d_in[1];
    const float* ew   = (const float*)d_in[2];
    const float* gW1  = (const float*)d_in[3];
    const float* gb1  = (const float*)d_in[4];
    const float* gW2  = (const float*)d_in[5];
    const float* gb2  = (const float*)d_in[6];
    const float* W0   = (const float*)d_in[7];
    const float* b0   = (const float*)d_in[8];
    const float* W1   = (const float*)d_in[9];
    const float* b1   = (const float*)d_in[10];
    const float* W2   = (const float*)d_in[11];
    const float* b2   = (const float*)d_in[12];
    const float* W3   = (const float*)d_in[13];
    const float* b3   = (const float*)d_in[14];
    float* out = (float*)d_out;

    const int N = in_sizes[0] / 512;          // 50000
    const int E = in_sizes[2];                // 1600000

    const int* erow = ei;        // edge_index[0] = source
    const int* ecol = ei + E;    // edge_index[1] = target

    float *bufA, *bufB, *dinv, *nrm_s;
    int *cnt, *off, *cur, *parts, *src_s;
    cudaGetSymbolAddress((void**)&bufA, g_buf_a);
    cudaGetSymbolAddress((void**)&bufB, g_buf_b);
    cudaGetSymbolAddress((void**)&dinv, g_dinv);
    cudaGetSymbolAddress((void**)&cnt,  g_cnt);
    cudaGetSymbolAddress((void**)&off,  g_off);
    cudaGetSymbolAddress((void**)&cur,  g_cur);
    cudaGetSymbolAddress((void**)&parts, g_parts);
    cudaGetSymbolAddress((void**)&src_s, g_src_s);
    cudaGetSymbolAddress((void**)&nrm_s, g_nrm_s);

    const int TPB = 256;
    const int gemm_blocks = (N + 63) / 64;
    const int edge_blocks = (E + TPB - 1) / TPB;
    const int n_blocks    = (N + TPB - 1) / TPB;
    const int scan_blocks = (N + SCAN_B - 1) / SCAN_B;
    const long long gat_threads = (long long)N * 16;
    const int gat_blocks = (int)((gat_threads + TPB - 1) / TPB);

    // --- degree + CSR build ---
    init_kernel<<<n_blocks, TPB>>>(dinv, cnt, N);
    count_deg_kernel<<<edge_blocks, TPB>>>(ecol, ew, dinv, cnt, E);
    deg_inv_kernel<<<n_blocks, TPB>>>(dinv, N);
    scan1_kernel<<<scan_blocks, SCAN_B>>>(cnt, off, parts, N);
    scan2_kernel<<<1, 32>>>(parts, scan_blocks);
    scan3_kernel<<<n_blocks, TPB>>>(off, parts, cur, N, E);
    fill_kernel<<<edge_blocks, TPB>>>(erow, ecol, ew, dinv, off, cur, src_s, nrm_s, E);

    // --- GCN layer 1: gemm then atomic-free CSR gather ---
    gemm_kernel<512, false><<<gemm_blocks, TPB>>>(x, gW1, nullptr, bufA, N);
    gather_kernel<<<gat_blocks, TPB>>>(bufA, src_s, nrm_s, off, dinv, bufB, N);

    // --- GCN layer 2: gemm reads selu(bufB + gb1) on the fly ---
    gemm_kernel<64, true><<<gemm_blocks, TPB>>>(bufB, gW2, gb1, bufA, N);
    gather_kernel<<<gat_blocks, TPB>>>(bufA, src_s, nrm_s, off, dinv, bufB, N);

    // --- Fused MLP: selu(bufB + gb2) -> 4 layers -> out ---
    fused_mlp_kernel<<<gemm_blocks, TPB>>>(bufB, gb2,
                                           W0, b0, W1, b1, W2, b2, W3, b3,
                                           out, N);
}

// round 16
// speedup vs baseline: 1.1358x; 1.1358x over previous
#include <cuda_runtime.h>
#include <cuda_bf16.h>
#include <cstdint>

// ---------------------------------------------------------------------------
// Problem constants: N=50000 nodes, E=1.6M edges, D_IN=512, H=64, D_OUT=64.
// ---------------------------------------------------------------------------
#define MAX_N 50048
#define MAX_E 1600000
#define HDIM  64
#define SCAN_B 512
#define DIN   512

// Scratch (device globals — allocation-free rule)
__device__ __align__(256) float g_buf_a[MAX_N * HDIM];   // xW
__device__ __align__(256) float g_buf_b[MAX_N * HDIM];   // agg
__device__ __align__(256) float g_dinv[MAX_N];           // deg^{-1/2}
__device__ __align__(256) int   g_cnt[MAX_N];            // in-degree counts
__device__ __align__(256) int   g_off[MAX_N + 1];        // CSR offsets
__device__ __align__(256) int   g_cur[MAX_N];            // fill cursors
__device__ __align__(256) int   g_parts[256];            // scan partials
__device__ __align__(256) int   g_src_s[MAX_E];          // CSR: source node
__device__ __align__(256) float g_nrm_s[MAX_E];          // CSR: edge norm
__device__ __align__(256) unsigned short g_w_hi[DIN * HDIM];  // gW1 hi (bf16 bits)
__device__ __align__(256) unsigned short g_w_lo[DIN * HDIM];  // gW1 lo (bf16 bits)

// ---------------------------------------------------------------------------
__device__ __forceinline__ float selu_f(float x) {
    const float sc = 1.0507009873554805f;
    const float al = 1.6732632423543772f;
    return x > 0.0f ? sc * x : sc * al * (expf(x) - 1.0f);
}

// ---------------------------------------------------------------------------
// mma.sync bf16 helpers (HMMA tensor path; register-resident accumulators)
// ---------------------------------------------------------------------------
__device__ __forceinline__ void mma_bf16(float* c, const unsigned* a, const unsigned* b) {
    asm volatile(
        "mma.sync.aligned.m16n8k16.row.col.f32.bf16.bf16.f32 "
        "{%0,%1,%2,%3}, {%4,%5,%6,%7}, {%8,%9}, {%0,%1,%2,%3};"
        : "+f"(c[0]), "+f"(c[1]), "+f"(c[2]), "+f"(c[3])
        : "r"(a[0]), "r"(a[1]), "r"(a[2]), "r"(a[3]), "r"(b[0]), "r"(b[1]));
}
__device__ __forceinline__ void ldsm_x4(unsigned* r, unsigned addr) {
    asm volatile("ldmatrix.sync.aligned.m8n8.x4.shared.b16 {%0,%1,%2,%3}, [%4];"
        : "=r"(r[0]), "=r"(r[1]), "=r"(r[2]), "=r"(r[3]) : "r"(addr));
}
__device__ __forceinline__ void ldsm_x4_t(unsigned* r, unsigned addr) {
    asm volatile("ldmatrix.sync.aligned.m8n8.x4.trans.shared.b16 {%0,%1,%2,%3}, [%4];"
        : "=r"(r[0]), "=r"(r[1]), "=r"(r[2]), "=r"(r[3]) : "r"(addr));
}

// split fp32 -> (hi, lo) bf16 bit patterns; hi+lo ≈ v to ~2^-17 relative.
__device__ __forceinline__ void split_bf16(float v, unsigned short& hi, unsigned short& lo) {
    __nv_bfloat16 h = __float2bfloat16_rn(v);
    __nv_bfloat16 l = __float2bfloat16_rn(v - __bfloat162float(h));
    hi = __bfloat16_as_ushort(h);
    lo = __bfloat16_as_ushort(l);
}

// One-time (per launch) split of gW1 [512,64] into bf16 hi/lo arrays.
__global__ void convert_w_kernel(const float* __restrict__ W,
                                 unsigned short* __restrict__ whi,
                                 unsigned short* __restrict__ wlo, int total) {
    int i = blockIdx.x * blockDim.x + threadIdx.x;
    if (i < total) {
        unsigned short h, l;
        split_bf16(W[i], h, l);
        whi[i] = h;
        wlo[i] = l;
    }
}

// ---------------------------------------------------------------------------
// GEMM1 via tensor cores: C[M x 64] = x[M x 512] @ gW1[512 x 64], fp32 in/out.
// In-kernel hi/lo bf16 split of the A tile (no extra global traffic); W comes
// pre-split. 3-product split: hi*hi + hi*lo + lo*hi (lo*lo ~2^-18, dropped).
// Block: 64 rows x 64 cols, 256 thr = 8 warps (2 m-warps x 4 n-warps),
// warp tile 32x16, BK=64 chunks (8 iters over K=512).
// ---------------------------------------------------------------------------
#define AP 72   // padded row stride in bf16 units (144 B = 9*16, LDSM-aligned)

__global__ void __launch_bounds__(256)
gemm1_hmma_kernel(const float* __restrict__ A,
                  const unsigned short* __restrict__ whi,
                  const unsigned short* __restrict__ wlo,
                  float* __restrict__ C, int M) {
    __shared__ unsigned short Ah[64][AP];
    __shared__ unsigned short Al[64][AP];
    __shared__ unsigned short Bh[64][AP];
    __shared__ unsigned short Bl[64][AP];

    const int tid  = threadIdx.x;
    const int lane = tid & 31;
    const int wid  = tid >> 5;
    const int warpN = wid & 3;       // 0..3 -> 16-col slabs
    const int warpM = wid >> 2;      // 0..1 -> 32-row slabs
    const int row0 = blockIdx.x * 64;

    // A staging mapping: row = tid>>2 (0..63), k quadrant = (tid&3)*16
    const int a_row = tid >> 2;
    const int a_kq  = (tid & 3) * 16;
    // B staging mapping: uint4 copy, 2 per thread per matrix
    // idx -> row = idx>>3, part = idx&7 (8 bf16 per uint4)

    float acc[2][2][4];
#pragma unroll
    for (int i = 0; i < 2; i++)
#pragma unroll
        for (int j = 0; j < 2; j++)
#pragma unroll
            for (int q = 0; q < 4; q++) acc[i][j][q] = 0.0f;

    // ldmatrix source addresses (fixed per thread, per kt offset applied later)
    const int lm_row = lane & 15;
    const int lm_col = (lane >> 4) * 8;

    for (int k0 = 0; k0 < DIN; k0 += 64) {
        // ---- stage A: load fp32, split to bf16 hi/lo in smem ----
#pragma unroll
        for (int q = 0; q < 4; q++) {
            int k = a_kq + q * 4;
            int grow = row0 + a_row;
            float4 v = make_float4(0.f, 0.f, 0.f, 0.f);
            if (grow < M)
                v = *reinterpret_cast<const float4*>(A + (size_t)grow * DIN + k0 + k);
            unsigned short h0, l0, h1, l1, h2, l2, h3, l3;
            split_bf16(v.x, h0, l0);
            split_bf16(v.y, h1, l1);
            split_bf16(v.z, h2, l2);
            split_bf16(v.w, h3, l3);
            unsigned hi01 = (unsigned)h0 | ((unsigned)h1 << 16);
            unsigned hi23 = (unsigned)h2 | ((unsigned)h3 << 16);
            unsigned lo01 = (unsigned)l0 | ((unsigned)l1 << 16);
            unsigned lo23 = (unsigned)l2 | ((unsigned)l3 << 16);
            *reinterpret_cast<unsigned*>(&Ah[a_row][k])     = hi01;
            *reinterpret_cast<unsigned*>(&Ah[a_row][k + 2]) = hi23;
            *reinterpret_cast<unsigned*>(&Al[a_row][k])     = lo01;
            *reinterpret_cast<unsigned*>(&Al[a_row][k + 2]) = lo23;
        }
        // ---- stage B: copy pre-split W chunk [k0..k0+63][0..63] ----
#pragma unroll
        for (int p = 0; p < 2; p++) {
            int idx = tid + p * 256;           // 0..511
            int brow = idx >> 3;
            int bpart = idx & 7;
            const uint4* srcH = reinterpret_cast<const uint4*>(whi + (size_t)(k0 + brow) * 64 + bpart * 8);
            const uint4* srcL = reinterpret_cast<const uint4*>(wlo + (size_t)(k0 + brow) * 64 + bpart * 8);
            *reinterpret_cast<uint4*>(&Bh[brow][bpart * 8]) = *srcH;
            *reinterpret_cast<uint4*>(&Bl[brow][bpart * 8]) = *srcL;
        }
        __syncthreads();

        // ---- compute: 4 k16 steps ----
#pragma unroll
        for (int kt = 0; kt < 4; kt++) {
            unsigned a_hi[2][4], a_lo[2][4];
#pragma unroll
            for (int mt = 0; mt < 2; mt++) {
                int r = warpM * 32 + mt * 16 + lm_row;
                int c = kt * 16 + lm_col;
                ldsm_x4(a_hi[mt], (unsigned)__cvta_generic_to_shared(&Ah[r][c]));
                ldsm_x4(a_lo[mt], (unsigned)__cvta_generic_to_shared(&Al[r][c]));
            }
            unsigned b_hi[4], b_lo[4];
            {
                int r = kt * 16 + lm_row;
                int c = warpN * 16 + lm_col;
                ldsm_x4_t(b_hi, (unsigned)__cvta_generic_to_shared(&Bh[r][c]));
                ldsm_x4_t(b_lo, (unsigned)__cvta_generic_to_shared(&Bl[r][c]));
            }
#pragma unroll
            for (int mt = 0; mt < 2; mt++)
#pragma unroll
                for (int nt = 0; nt < 2; nt++) {
                    mma_bf16(acc[mt][nt], a_hi[mt], &b_hi[nt * 2]);
                    mma_bf16(acc[mt][nt], a_hi[mt], &b_lo[nt * 2]);
                    mma_bf16(acc[mt][nt], a_lo[mt], &b_hi[nt * 2]);
                }
        }
        __syncthreads();
    }

    // ---- epilogue: c-frag m16n8 layout ----
    const int g   = lane >> 2;
    const int tig = lane & 3;
#pragma unroll
    for (int mt = 0; mt < 2; mt++) {
#pragma unroll
        for (int nt = 0; nt < 2; nt++) {
            int col = warpN * 16 + nt * 8 + tig * 2;
            int r0 = row0 + warpM * 32 + mt * 16 + g;
            int r1 = r0 + 8;
            if (r0 < M) {
                C[(size_t)r0 * 64 + col]     = acc[mt][nt][0];
                C[(size_t)r0 * 64 + col + 1] = acc[mt][nt][1];
            }
            if (r1 < M) {
                C[(size_t)r1 * 64 + col]     = acc[mt][nt][2];
                C[(size_t)r1 * 64 + col + 1] = acc[mt][nt][3];
            }
        }
    }
}

// ---------------------------------------------------------------------------
// Degree + in-degree count (one pass over edges)
// ---------------------------------------------------------------------------
__global__ void init_kernel(float* __restrict__ deg, int* __restrict__ cnt, int n) {
    int i = blockIdx.x * blockDim.x + threadIdx.x;
    if (i < n) { deg[i] = 1.0f; cnt[i] = 0; }   // deg starts at self-loop w=1
}

__global__ void count_deg_kernel(const int* __restrict__ col,
                                 const float* __restrict__ w,
                                 float* __restrict__ deg,
                                 int* __restrict__ cnt, int e) {
    int i = blockIdx.x * blockDim.x + threadIdx.x;
    if (i < e) {
        int c = col[i];
        atomicAdd(&deg[c], w[i]);
        atomicAdd(&cnt[c], 1);
    }
}

__global__ void deg_inv_kernel(float* __restrict__ deg, int n) {
    int i = blockIdx.x * blockDim.x + threadIdx.x;
    if (i < n) {
        float d = deg[i];
        deg[i] = d > 0.0f ? rsqrtf(d) : 0.0f;
    }
}

// ---------------------------------------------------------------------------
// Exclusive scan of cnt[0..n) into off[0..n], off[n]=e.  3 phases.
// ---------------------------------------------------------------------------
__global__ void scan1_kernel(const int* __restrict__ cnt, int* __restrict__ off,
                             int* __restrict__ partials, int n) {
    __shared__ int s[SCAN_B];
    int t = threadIdx.x;
    int idx = blockIdx.x * SCAN_B + t;
    int v = (idx < n) ? cnt[idx] : 0;
    s[t] = v;
    __syncthreads();
    for (int d = 1; d < SCAN_B; d <<= 1) {
        int x = (t >= d) ? s[t - d] : 0;
        __syncthreads();
        s[t] += x;
        __syncthreads();
    }
    if (idx < n) off[idx] = s[t] - v;          // exclusive within block
    if (t == SCAN_B - 1) partials[blockIdx.x] = s[t];  // block total
}

__global__ void scan2_kernel(int* __restrict__ partials, int nb) {
    if (threadIdx.x == 0 && blockIdx.x == 0) {
        int run = 0;
        for (int i = 0; i < nb; i++) {
            int v = partials[i];
            partials[i] = run;
            run += v;
        }
    }
}

__global__ void scan3_kernel(int* __restrict__ off, const int* __restrict__ partials,
                             int* __restrict__ cur, int n, int e) {
    int i = blockIdx.x * blockDim.x + threadIdx.x;
    if (i < n) {
        off[i] += partials[i / SCAN_B];
        cur[i] = 0;
    }
    if (i == 0) off[n] = e;
}

// ---------------------------------------------------------------------------
// CSR fill: place each edge into its destination's segment; norm inline.
// ---------------------------------------------------------------------------
__global__ void fill_kernel(const int* __restrict__ row, const int* __restrict__ col,
                            const float* __restrict__ w, const float* __restrict__ dinv,
                            const int* __restrict__ off, int* __restrict__ cur,
                            int* __restrict__ src_s, float* __restrict__ nrm_s, int e) {
    int i = blockIdx.x * blockDim.x + threadIdx.x;
    if (i < e) {
        int r = row[i];
        int c = col[i];
        int slot = off[c] + atomicAdd(&cur[c], 1);
        src_s[slot] = r;
        nrm_s[slot] = __ldg(dinv + r) * w[i] * __ldg(dinv + c);
    }
}

// ---------------------------------------------------------------------------
// Tiled SGEMM (fp32): C[M x 64] = A'[M x K] @ B[K x 64], A' = A or
// selu(A + biasIn) when PREACT.  Used for GCN layer 2 (K=64).
// ---------------------------------------------------------------------------
template <int K, bool PREACT>
__global__ void __launch_bounds__(256)
gemm_kernel(const float* __restrict__ A, const float* __restrict__ B,
            const float* __restrict__ biasIn, float* __restrict__ C, int M) {
    constexpr int BM = 64, BN = 64, BK = 32;
    __shared__ float As[BK][BM + 1];
    __shared__ float Bs[BK][BN];

    const int tid = threadIdx.x;
    const int tx = tid & 15;
    const int ty = tid >> 4;
    const int row0 = blockIdx.x * BM;

    const int ar = tid >> 3;           // 0..31
    const int ac = (tid & 7) * 4;      // 0..28
    const int br = tid >> 4;           // 0..15
    const int bc = (tid & 15) * 4;     // 0..60

    float acc[4][4];
#pragma unroll
    for (int i = 0; i < 4; i++)
#pragma unroll
        for (int j = 0; j < 4; j++) acc[i][j] = 0.0f;

    for (int k0 = 0; k0 < K; k0 += BK) {
#pragma unroll
        for (int h = 0; h < 2; h++) {
            int r = ar + h * 32;
            int grow = row0 + r;
            float4 v = make_float4(0.f, 0.f, 0.f, 0.f);
            if (grow < M)
                v = *reinterpret_cast<const float4*>(A + (size_t)grow * K + k0 + ac);
            if (PREACT) {
                float4 b = *reinterpret_cast<const float4*>(biasIn + k0 + ac);
                v.x = selu_f(v.x + b.x);
                v.y = selu_f(v.y + b.y);
                v.z = selu_f(v.z + b.z);
                v.w = selu_f(v.w + b.w);
            }
            As[ac + 0][r] = v.x;
            As[ac + 1][r] = v.y;
            As[ac + 2][r] = v.z;
            As[ac + 3][r] = v.w;
        }
#pragma unroll
        for (int h = 0; h < 2; h++) {
            int r = br + h * 16;
            float4 v = *reinterpret_cast<const float4*>(B + (size_t)(k0 + r) * BN + bc);
            *reinterpret_cast<float4*>(&Bs[r][bc]) = v;
        }
        __syncthreads();

#pragma unroll
        for (int kk = 0; kk < BK; kk++) {
            float a[4];
#pragma unroll
            for (int i = 0; i < 4; i++) a[i] = As[kk][ty * 4 + i];
            float4 b4 = *reinterpret_cast<const float4*>(&Bs[kk][tx * 4]);
            float b[4] = {b4.x, b4.y, b4.z, b4.w};
#pragma unroll
            for (int i = 0; i < 4; i++)
#pragma unroll
                for (int j = 0; j < 4; j++) acc[i][j] += a[i] * b[j];
        }
        __syncthreads();
    }

#pragma unroll
    for (int i = 0; i < 4; i++) {
        int gr = row0 + ty * 4 + i;
        if (gr >= M) continue;
#pragma unroll
        for (int j = 0; j < 4; j++)
            C[(size_t)gr * 64 + tx * 4 + j] = acc[i][j];
    }
}

// ---------------------------------------------------------------------------
// CSR gather aggregation: one HALF-WARP per destination node, ZERO atomics.
// Each of 16 lanes owns one float4 of the 64 feature dims. Self-loop term
// folded in. Unroll-4 over incident edges for memory-level parallelism.
// ---------------------------------------------------------------------------
__global__ void __launch_bounds__(256)
gather_kernel(const float* __restrict__ xw,
              const int* __restrict__ src_s, const float* __restrict__ nrm_s,
              const int* __restrict__ off, const float* __restrict__ dinv,
              float* __restrict__ agg, int n) {
    int hw = (blockIdx.x * blockDim.x + threadIdx.x) >> 4;   // half-warp id = node
    int lane = threadIdx.x & 15;
    if (hw >= n) return;

    const float4* xw4 = reinterpret_cast<const float4*>(xw);

    int beg = __ldg(off + hw);
    int end = __ldg(off + hw + 1);

    // self-loop: xw[node] * dinv^2
    float d = __ldg(dinv + hw);
    float s = d * d;
    float4 a0 = __ldg(xw4 + (size_t)hw * 16 + lane);
    float4 acc = make_float4(a0.x * s, a0.y * s, a0.z * s, a0.w * s);

    int i = beg;
    for (; i + 4 <= end; i += 4) {
        int s0 = __ldg(src_s + i + 0);
        int s1 = __ldg(src_s + i + 1);
        int s2 = __ldg(src_s + i + 2);
        int s3 = __ldg(src_s + i + 3);
        float n0 = __ldg(nrm_s + i + 0);
        float n1 = __ldg(nrm_s + i + 1);
        float n2 = __ldg(nrm_s + i + 2);
        float n3 = __ldg(nrm_s + i + 3);
        float4 v0 = __ldg(xw4 + (size_t)s0 * 16 + lane);
        float4 v1 = __ldg(xw4 + (size_t)s1 * 16 + lane);
        float4 v2 = __ldg(xw4 + (size_t)s2 * 16 + lane);
        float4 v3 = __ldg(xw4 + (size_t)s3 * 16 + lane);
        acc.x += n0 * v0.x + n1 * v1.x + n2 * v2.x + n3 * v3.x;
        acc.y += n0 * v0.y + n1 * v1.y + n2 * v2.y + n3 * v3.y;
        acc.z += n0 * v0.z + n1 * v1.z + n2 * v2.z + n3 * v3.z;
        acc.w += n0 * v0.w + n1 * v1.w + n2 * v2.w + n3 * v3.w;
    }
    for (; i < end; i++) {
        int sr = __ldg(src_s + i);
        float nm = __ldg(nrm_s + i);
        float4 v = __ldg(xw4 + (size_t)sr * 16 + lane);
        acc.x += nm * v.x;
        acc.y += nm * v.y;
        acc.z += nm * v.z;
        acc.w += nm * v.w;
    }

    reinterpret_cast<float4*>(agg + (size_t)hw * 64)[lane] = acc;
}

// ---------------------------------------------------------------------------
// Fused MLP: out = selu(selu(selu(selu(agg+gb)W0+b0)W1+b1)W2+b2)W3+b3
// One block = 64 rows; 33 KB static smem (single in-place Hs buffer).
// ---------------------------------------------------------------------------
__global__ void __launch_bounds__(256)
fused_mlp_kernel(const float* __restrict__ agg, const float* __restrict__ gb,
                 const float* __restrict__ W0, const float* __restrict__ b0,
                 const float* __restrict__ W1, const float* __restrict__ b1,
                 const float* __restrict__ W2, const float* __restrict__ b2,
                 const float* __restrict__ W3, const float* __restrict__ b3,
                 float* __restrict__ out, int M) {
    __shared__ float Hs[HDIM][HDIM + 1];  // [k][row], transposed, padded
    __shared__ float Ws[HDIM][HDIM];      // [k][out]

    const int tid = threadIdx.x;
    const int tx = tid & 15;
    const int ty = tid >> 4;
    const int row0 = blockIdx.x * 64;

    {
        const int lr = tid >> 2;
        const int lc = (tid & 3) * 16;
        int grow = row0 + lr;
#pragma unroll
        for (int q = 0; q < 4; q++) {
            int k = lc + q * 4;
            float4 v = make_float4(0.f, 0.f, 0.f, 0.f);
            if (grow < M)
                v = *reinterpret_cast<const float4*>(agg + (size_t)grow * 64 + k);
            float4 b = *reinterpret_cast<const float4*>(gb + k);
            Hs[k + 0][lr] = selu_f(v.x + b.x);
            Hs[k + 1][lr] = selu_f(v.y + b.y);
            Hs[k + 2][lr] = selu_f(v.z + b.z);
            Hs[k + 3][lr] = selu_f(v.w + b.w);
        }
    }

    const float* Wl[4] = {W0, W1, W2, W3};
    const float* bl[4] = {b0, b1, b2, b3};

    for (int layer = 0; layer < 4; layer++) {
        {
            const int lr = tid >> 2;
            const int lc = (tid & 3) * 16;
            const float* W = Wl[layer];
#pragma unroll
            for (int q = 0; q < 4; q++) {
                int c0 = lc + q * 4;
                *reinterpret_cast<float4*>(&Ws[lr][c0]) =
                    *reinterpret_cast<const float4*>(W + (size_t)lr * 64 + c0);
            }
        }
        __syncthreads();

        float acc[4][4];
#pragma unroll
        for (int i = 0; i < 4; i++)
#pragma unroll
            for (int j = 0; j < 4; j++) acc[i][j] = 0.0f;

#pragma unroll 16
        for (int kk = 0; kk < HDIM; kk++) {
            float a[4];
#pragma unroll
            for (int i = 0; i < 4; i++) a[i] = Hs[kk][ty * 4 + i];
            float4 b4 = *reinterpret_cast<const float4*>(&Ws[kk][tx * 4]);
            float b[4] = {b4.x, b4.y, b4.z, b4.w};
#pragma unroll
            for (int i = 0; i < 4; i++)
#pragma unroll
                for (int j = 0; j < 4; j++) acc[i][j] += a[i] * b[j];
        }

        float4 bb = *reinterpret_cast<const float4*>(bl[layer] + tx * 4);
        float bias4[4] = {bb.x, bb.y, bb.z, bb.w};

        if (layer < 3) {
            __syncthreads();
#pragma unroll
            for (int i = 0; i < 4; i++)
#pragma unroll
                for (int j = 0; j < 4; j++)
                    Hs[tx * 4 + j][ty * 4 + i] = selu_f(acc[i][j] + bias4[j]);
            __syncthreads();
        } else {
#pragma unroll
            for (int i = 0; i < 4; i++) {
                int gr = row0 + ty * 4 + i;
                if (gr >= M) continue;
#pragma unroll
                for (int j = 0; j < 4; j++)
                    out[(size_t)gr * 64 + tx * 4 + j] = acc[i][j] + bias4[j];
            }
        }
    }
}

// ---------------------------------------------------------------------------
// Launch.  Inputs (metadata order):
//  0 x[N,512] 1 edge_index[2,E] 2 edge_attrs[E]
//  3 gW1 4 gb1 5 gW2 6 gb2 7 W0 8 b0 9 W1 10 b1 11 W2 12 b2 13 W3 14 b3
// Output: float32 [N,64]
// ---------------------------------------------------------------------------
extern "C" void kernel_launch(void* const* d_in, const int* in_sizes, int n_in,
                              void* d_out, int out_size) {
    const float* x    = (const float*)d_in[0];
    const int*   ei   = (const int*)d_in[1];
    const float* ew   = (const float*)d_in[2];
    const float* gW1  = (const float*)d_in[3];
    const float* gb1  = (const float*)d_in[4];
    const float* gW2  = (const float*)d_in[5];
    const float* gb2  = (const float*)d_in[6];
    const float* W0   = (const float*)d_in[7];
    const float* b0   = (const float*)d_in[8];
    const float* W1   = (const float*)d_in[9];
    const float* b1   = (const float*)d_in[10];
    const float* W2   = (const float*)d_in[11];
    const float* b2   = (const float*)d_in[12];
    const float* W3   = (const float*)d_in[13];
    const float* b3   = (const float*)d_in[14];
    float* out = (float*)d_out;

    const int N = in_sizes[0] / 512;          // 50000
    const int E = in_sizes[2];                // 1600000

    const int* erow = ei;        // edge_index[0] = source
    const int* ecol = ei + E;    // edge_index[1] = target

    float *bufA, *bufB, *dinv, *nrm_s;
    int *cnt, *off, *cur, *parts, *src_s;
    unsigned short *whi, *wlo;
    cudaGetSymbolAddress((void**)&bufA, g_buf_a);
    cudaGetSymbolAddress((void**)&bufB, g_buf_b);
    cudaGetSymbolAddress((void**)&dinv, g_dinv);
    cudaGetSymbolAddress((void**)&cnt,  g_cnt);
    cudaGetSymbolAddress((void**)&off,  g_off);
    cudaGetSymbolAddress((void**)&cur,  g_cur);
    cudaGetSymbolAddress((void**)&parts, g_parts);
    cudaGetSymbolAddress((void**)&src_s, g_src_s);
    cudaGetSymbolAddress((void**)&nrm_s, g_nrm_s);
    cudaGetSymbolAddress((void**)&whi, g_w_hi);
    cudaGetSymbolAddress((void**)&wlo, g_w_lo);

    const int TPB = 256;
    const int gemm_blocks = (N + 63) / 64;
    const int edge_blocks = (E + TPB - 1) / TPB;
    const int n_blocks    = (N + TPB - 1) / TPB;
    const int scan_blocks = (N + SCAN_B - 1) / SCAN_B;
    const long long gat_threads = (long long)N * 16;
    const int gat_blocks = (int)((gat_threads + TPB - 1) / TPB);
    const int wconv_blocks = (DIN * HDIM + TPB - 1) / TPB;

    // --- split gW1 into bf16 hi/lo (tiny, once per launch) ---
    convert_w_kernel<<<wconv_blocks, TPB>>>(gW1, whi, wlo, DIN * HDIM);

    // --- degree + CSR build ---
    init_kernel<<<n_blocks, TPB>>>(dinv, cnt, N);
    count_deg_kernel<<<edge_blocks, TPB>>>(ecol, ew, dinv, cnt, E);
    deg_inv_kernel<<<n_blocks, TPB>>>(dinv, N);
    scan1_kernel<<<scan_blocks, SCAN_B>>>(cnt, off, parts, N);
    scan2_kernel<<<1, 32>>>(parts, scan_blocks);
    scan3_kernel<<<n_blocks, TPB>>>(off, parts, cur, N, E);
    fill_kernel<<<edge_blocks, TPB>>>(erow, ecol, ew, dinv, off, cur, src_s, nrm_s, E);

    // --- GCN layer 1: tensor-core GEMM (bf16 hi/lo split) then CSR gather ---
    gemm1_hmma_kernel<<<gemm_blocks, TPB>>>(x, whi, wlo, bufA, N);
    gather_kernel<<<gat_blocks, TPB>>>(bufA, src_s, nrm_s, off, dinv, bufB, N);

    // --- GCN layer 2: fp32 gemm reads selu(bufB + gb1) on the fly ---
    gemm_kernel<64, true><<<gemm_blocks, TPB>>>(bufB, gW2, gb1, bufA, N);
    gather_kernel<<<gat_blocks, TPB>>>(bufA, src_s, nrm_s, off, dinv, bufB, N);

    // --- Fused MLP: selu(bufB + gb2) -> 4 layers -> out ---
    fused_mlp_kernel<<<gemm_blocks, TPB>>>(bufB, gb2,
                                           W0, b0, W1, b1, W2, b2, W3, b3,
                                           out, N);
}